// round 4
// baseline (speedup 1.0000x reference)
#include <cuda_runtime.h>
#include <cstdint>
#include <cstddef>

// Problem constants
#define Bq 2
#define Nq 8192
#define Cq 32
#define Kq 16
#define Rq 4
#define Hq 512
#define CFq 106
#define CKq (Bq*Nq*Kq)         // 262144 total (n,k) columns
#define NRq (Bq*Nq*Rq)         // 65536 total (n,r) columns
#define OF_BASE (Bq*Nq*Rq*3)   // 196608 floats of coarse_xyz before output_feature

// ---------------- scratch (device globals; no allocation) ----------------
__device__ int   g_idx[Bq*Nq*Kq];              // knn indices, sorted by (d, idx)
__device__ float g_fmat[(size_t)CFq*CKq];      // Fmat [cf][col], col=(b*N+n)*16+k
__device__ float g_rmat[(size_t)CFq*NRq];      // Rmat [cf][col], col=(b*N+n)*4+r
__device__ float g_hl[(size_t)(2*Hq)*CKq];     // rows 0..511 = h, 512..1023 = l
__device__ float g_gm[(size_t)Hq*NRq];         // g

// TF32 rounding (emulates cuBLAS/tensor-core operand conversion).
// cvt.rna.tf32.f32 writes a .b32 destination.
__device__ __forceinline__ float tf32r(float x) {
    uint32_t u;
    asm("cvt.rna.tf32.f32 %0, %1;" : "=r"(u) : "f"(x));
    return __uint_as_float(u);
}

// order-preserving float->uint key
__device__ __forceinline__ unsigned fkey(float d) {
    unsigned u = __float_as_uint(d);
    return (u & 0x80000000u) ? ~u : (u | 0x80000000u);
}

// ---------------- K1: KNN (one warp per query point), exact fp32 ----------
// Reference distance path is effectively exact fp32 (K=3 contraction is not
// TF32). Self is always rank 0, so exclude m==n and take top-16 by (d, idx).
__global__ __launch_bounds__(256) void knn_kernel(const float* __restrict__ xyz) {
    int warp = (blockIdx.x * blockDim.x + threadIdx.x) >> 5;
    int lane = threadIdx.x & 31;
    int b = warp >> 13;
    int n = warp & (Nq - 1);
    const float* xb = xyz + (size_t)b * Nq * 3;
    float qx = xb[n*3+0], qy = xb[n*3+1], qz = xb[n*3+2];
    float sqn = __fmaf_rn(qz, qz, __fmaf_rn(qy, qy, __fmul_rn(qx, qx)));

    float kd[Kq];
    int   ki[Kq];
#pragma unroll
    for (int i = 0; i < Kq; i++) { kd[i] = 1e30f; ki[i] = 0x7fffffff; }

    for (int m = lane; m < Nq; m += 32) {
        if (m == n) continue;
        float px = xb[m*3+0], py = xb[m*3+1], pz = xb[m*3+2];
        float sqm = __fmaf_rn(pz, pz, __fmaf_rn(py, py, __fmul_rn(px, px)));
        float dot = __fmaf_rn(qz, pz, __fmaf_rn(qy, py, __fmul_rn(qx, px)));
        float d = __fsub_rn(__fadd_rn(sqn, sqm), __fmul_rn(2.0f, dot));
        if (d < kd[Kq-1] || (d == kd[Kq-1] && m < ki[Kq-1])) {
            int j = Kq - 1;
            while (j > 0 && (kd[j-1] > d || (kd[j-1] == d && ki[j-1] > m))) {
                kd[j] = kd[j-1]; ki[j] = ki[j-1]; j--;
            }
            kd[j] = d; ki[j] = m;
        }
    }

    // merge 32 sorted per-lane lists -> global top-16 in order
    int p = 0;
    for (int t = 0; t < Kq; t++) {
        float myd; int myi;
        if (p < Kq) { myd = kd[p]; myi = ki[p]; } else { myd = 1e38f; myi = 0x7fffffff; }
        unsigned long long key = (((unsigned long long)fkey(myd)) << 32) | (unsigned)myi;
        unsigned long long mk = key;
#pragma unroll
        for (int off = 16; off; off >>= 1) {
            unsigned long long o = __shfl_xor_sync(0xffffffffu, mk, off);
            if (o < mk) mk = o;
        }
        if (mk == key) p++;
        if (lane == 0) g_idx[warp * Kq + t] = (int)(unsigned)(mk & 0xffffffffu);
    }
}

// ---------------- K2: build Fmat (thread per (b,n,k) column) ----------------
__global__ __launch_bounds__(256) void fmat_kernel(const float* __restrict__ xyz,
                                                   const float* __restrict__ f) {
    int j = blockIdx.x * blockDim.x + threadIdx.x;   // 0..262143
    int n = (j >> 4) & (Nq - 1);
    int b = j >> 17;
    int m = g_idx[j];
    const float* xb = xyz + (size_t)b * Nq * 3;
    float cx = xb[n*3+0], cy = xb[n*3+1], cz = xb[n*3+2];
    float px = xb[m*3+0], py = xb[m*3+1], pz = xb[m*3+2];
    float dx = px - cx, dy = py - cy, dz = pz - cz;
    float dist = sqrtf(dx*dx + dy*dy + dz*dz);

    const float* fb = f + (size_t)b * Cq * Nq;
#pragma unroll 4
    for (int c = 0; c < Cq; c++) {
        float gf  = fb[c*Nq + m];
        float cfv = fb[c*Nq + n];
        g_fmat[(size_t)c*CKq + j]        = gf;
        g_fmat[(size_t)(Cq + c)*CKq + j] = cfv;
        g_fmat[(size_t)(2*Cq + c)*CKq + j] = cfv - gf;
    }
    g_fmat[(size_t)96*CKq + j] = dx;
    g_fmat[(size_t)97*CKq + j] = dy;
    g_fmat[(size_t)98*CKq + j] = dz;
    g_fmat[(size_t)99*CKq + j] = px;
    g_fmat[(size_t)100*CKq + j] = py;
    g_fmat[(size_t)101*CKq + j] = pz;
    g_fmat[(size_t)102*CKq + j] = cx;
    g_fmat[(size_t)103*CKq + j] = cy;
    g_fmat[(size_t)104*CKq + j] = cz;
    g_fmat[(size_t)105*CKq + j] = dist;
}

// ---------------- K3: gather R columns from Fmat via r_indice ----------------
__global__ __launch_bounds__(256) void rgather_kernel(const int* __restrict__ rind) {
    int e = blockIdx.x * blockDim.x + threadIdx.x;
    if (e >= CFq * NRq) return;
    int cf  = e >> 16;            // NRq == 65536
    int col = e & (NRq - 1);      // (b*N+n)*4 + r
    int nb  = col >> 2;
    int r   = col & 3;
    int b   = nb >> 13;
    int n   = nb & (Nq - 1);
    int ri  = rind[(((size_t)b*CFq + cf)*Nq + n)*Rq + r];   // in [0,16)
    g_rmat[(size_t)cf*NRq + col] = g_fmat[(size_t)cf*CKq + (size_t)nb*Kq + ri];
}

// ---------------- K4: tiled TF32-emulated GEMM + bias + ReLU ----------------
// MODE 0: [Wh;Wl] @ Fmat -> g_hl (M=1024, NC=CKq). MODE 1: Wg @ Rmat -> g_gm.
template <int MODE>
__global__ __launch_bounds__(256) void gemm_relu_kernel(
    const float* __restrict__ W0, const float* __restrict__ b0,
    const float* __restrict__ W1, const float* __restrict__ b1)
{
    const int NC = (MODE == 0) ? CKq : NRq;
    const float* __restrict__ Bm = (MODE == 0) ? g_fmat : g_rmat;
    float* __restrict__ Out = (MODE == 0) ? g_hl : g_gm;

    __shared__ float As[128][54];   // 53 cf slice (+1 pad)
    __shared__ float Bs[53][64];

    int row0 = blockIdx.x * 128;
    int col0 = blockIdx.y * 64;

    const float* W;
    const float* bias;
    if (MODE == 0 && row0 >= Hq) { W = W1 + (size_t)(row0 - Hq)*CFq; bias = b1 + (row0 - Hq); }
    else                         { W = W0 + (size_t)row0*CFq;        bias = b0 + row0; }

    int tid = threadIdx.x;
    int tr = tid >> 4;        // 0..15 -> 8 rows each
    int tc = tid & 15;        // 0..15 -> 4 cols each

    float acc[8][4];
#pragma unroll
    for (int ii = 0; ii < 8; ii++)
#pragma unroll
        for (int jj = 0; jj < 4; jj++) acc[ii][jj] = 0.0f;

    for (int kp = 0; kp < 2; kp++) {
        int cfb = kp * 53;
        if (kp) __syncthreads();
        for (int i = tid; i < 128*53; i += 256) {
            int r = i / 53; int cf = i - r*53;
            As[r][cf] = tf32r(W[(size_t)r*CFq + cfb + cf]);
        }
        for (int i = tid; i < 53*64; i += 256) {
            int cf = i >> 6; int c = i & 63;
            Bs[cf][c] = tf32r(Bm[(size_t)(cfb + cf)*NC + col0 + c]);
        }
        __syncthreads();
#pragma unroll 1
        for (int cf = 0; cf < 53; cf++) {
            const float4 bv = *(const float4*)&Bs[cf][tc*4];
#pragma unroll
            for (int ii = 0; ii < 8; ii++) {
                float av = As[tr*8 + ii][cf];
                acc[ii][0] = fmaf(av, bv.x, acc[ii][0]);
                acc[ii][1] = fmaf(av, bv.y, acc[ii][1]);
                acc[ii][2] = fmaf(av, bv.z, acc[ii][2]);
                acc[ii][3] = fmaf(av, bv.w, acc[ii][3]);
            }
        }
    }

#pragma unroll
    for (int ii = 0; ii < 8; ii++) {
        int row = row0 + tr*8 + ii;
        float bb = bias[tr*8 + ii];
        size_t ob = (size_t)row*NC + col0 + tc*4;
        float4 v;
        v.x = fmaxf(acc[ii][0] + bb, 0.0f);
        v.y = fmaxf(acc[ii][1] + bb, 0.0f);
        v.z = fmaxf(acc[ii][2] + bb, 0.0f);
        v.w = fmaxf(acc[ii][3] + bb, 0.0f);
        *(float4*)&Out[ob] = v;
    }
}

// ---------------- K5: finalize (lmax, scores, softmax, aff, outputs) ----------------
__global__ __launch_bounds__(128) void finalize_kernel(float* __restrict__ out) {
    __shared__ float gs[Hq][4];      // tf32-rounded g
    __shared__ float hs[Hq][16];     // tf32-rounded h
    __shared__ float gx[3][16];      // tf32-rounded grouped_xyz
    __shared__ float sc_part[128];

    int nb = blockIdx.x;               // b*N + n
    int b = nb >> 13;
    int n = nb & (Nq - 1);
    int tid = threadIdx.x;
    size_t cb = (size_t)nb * Kq;

    // phase A: load g, h (rounded); compute lmax from raw l; write l_prime
    for (int h = tid; h < Hq; h += 128) {
        float4 gv = *(const float4*)&g_gm[(size_t)h*NRq + (size_t)nb*Rq];
        gs[h][0] = tf32r(gv.x); gs[h][1] = tf32r(gv.y);
        gs[h][2] = tf32r(gv.z); gs[h][3] = tf32r(gv.w);
        float lmx = -3.4e38f;
#pragma unroll
        for (int q = 0; q < 4; q++) {
            float4 hv = *(const float4*)&g_hl[(size_t)h*CKq + cb + q*4];
            hs[h][q*4+0] = tf32r(hv.x); hs[h][q*4+1] = tf32r(hv.y);
            hs[h][q*4+2] = tf32r(hv.z); hs[h][q*4+3] = tf32r(hv.w);
            float4 lv = *(const float4*)&g_hl[(size_t)(Hq + h)*CKq + cb + q*4];
            lmx = fmaxf(lmx, fmaxf(fmaxf(lv.x, lv.y), fmaxf(lv.z, lv.w)));
        }
        float4 o; o.x = lmx; o.y = lmx; o.z = lmx; o.w = lmx;
        *(float4*)&out[OF_BASE + (((size_t)b*515 + h)*Nq + n)*Rq] = o;
    }
    if (tid < 48) {   // grouped_xyz rows 99..101
        int c = tid >> 4, k = tid & 15;
        gx[c][k] = tf32r(g_fmat[(size_t)(99 + c)*CKq + cb + k]);
    }
    __syncthreads();

    // phase B: scores[r][k] = sum_h g[h][r]*h[h][k] (tf32 operands, fp32 acc)
    {
        int rk = tid & 63;
        int half = tid >> 6;
        int r = rk >> 4, k = rk & 15;
        float s = 0.0f;
        int h0 = half * 256;
#pragma unroll 8
        for (int h = h0; h < h0 + 256; h++) s = fmaf(gs[h][r], hs[h][k], s);
        sc_part[tid] = s;
    }
    __syncthreads();

    if (tid < 64) {
        int r = tid >> 4, k = tid & 15;
        float sv = sc_part[tid] + sc_part[tid + 64];
        // softmax over k within 16-lane groups
        float mx = sv;
#pragma unroll
        for (int off = 8; off; off >>= 1) mx = fmaxf(mx, __shfl_xor_sync(0xffffffffu, mx, off));
        float e = expf(sv - mx);
        float sum = e;
#pragma unroll
        for (int off = 8; off; off >>= 1) sum += __shfl_xor_sync(0xffffffffu, sum, off);
        float sim = tf32r(e / sum);   // aff einsum rounds sim to tf32
        float a0 = sim * gx[0][k];
        float a1 = sim * gx[1][k];
        float a2 = sim * gx[2][k];
#pragma unroll
        for (int off = 8; off; off >>= 1) {
            a0 += __shfl_xor_sync(0xffffffffu, a0, off);
            a1 += __shfl_xor_sync(0xffffffffu, a1, off);
            a2 += __shfl_xor_sync(0xffffffffu, a2, off);
        }
        if (k == 0) {
            size_t cbase = ((size_t)b*(Nq*Rq) + (size_t)n*Rq + r) * 3;
            out[cbase + 0] = a0;
            out[cbase + 1] = a1;
            out[cbase + 2] = a2;
            out[OF_BASE + (((size_t)b*515 + 512)*Nq + n)*Rq + r] = a0;
            out[OF_BASE + (((size_t)b*515 + 513)*Nq + n)*Rq + r] = a1;
            out[OF_BASE + (((size_t)b*515 + 514)*Nq + n)*Rq + r] = a2;
        }
    }
}

// ---------------- launch ----------------
extern "C" void kernel_launch(void* const* d_in, const int* in_sizes, int n_in,
                              void* d_out, int out_size) {
    const float* xyz  = (const float*)d_in[0];
    const float* f    = (const float*)d_in[1];
    const float* Wg   = (const float*)d_in[2];
    const float* bg   = (const float*)d_in[3];
    const float* Wh   = (const float*)d_in[4];
    const float* bh   = (const float*)d_in[5];
    const float* Wl   = (const float*)d_in[6];
    const float* bl   = (const float*)d_in[7];
    const int*   rind = (const int*)d_in[8];
    float* out = (float*)d_out;

    knn_kernel<<<(Bq*Nq)/8, 256>>>(xyz);
    fmat_kernel<<<CKq/256, 256>>>(xyz, f);
    rgather_kernel<<<(CFq*NRq + 255)/256, 256>>>(rind);
    gemm_relu_kernel<0><<<dim3((2*Hq)/128, CKq/64), 256>>>(Wh, bh, Wl, bl);
    gemm_relu_kernel<1><<<dim3(Hq/128, NRq/64), 256>>>(Wg, bg, Wg, bg);
    finalize_kernel<<<Bq*Nq, 128>>>(out);
}

// round 7
// speedup vs baseline: 1.3513x; 1.3513x over previous
#include <cuda_runtime.h>
#include <cstdint>
#include <cstddef>

// Problem constants
#define Bq 2
#define Nq 8192
#define Cq 32
#define Kq 16
#define Rq 4
#define Hq 512
#define CFq 106
#define KPAD 112
#define CKq (Bq*Nq*Kq)         // 262144 total (n,k) columns
#define NRq (Bq*Nq*Rq)         // 65536 total (n,r) columns
#define NBq (Bq*Nq)            // 16384 points
#define OF_BASE (Bq*Nq*Rq*3)   // 196608 floats of coarse_xyz before output_feature

// ---------------- scratch (device globals; no allocation) ----------------
__device__ int   g_idx[Bq*Nq*Kq];              // knn indices, sorted by (d, idx)
__device__ float g_fmat[(size_t)CFq*CKq];      // Fmat [cf][col], col=(b*N+n)*16+k
__device__ float g_rmat[(size_t)CFq*NRq];      // Rmat [cf][col], col=(b*N+n)*4+r
__device__ float g_hl[(size_t)Hq*CKq];         // h rows only
__device__ float g_lmax[(size_t)NBq*Hq];       // max_k relu(l) : [point][h]
__device__ float g_gm[(size_t)Hq*NRq];         // g

// TF32 rounding (emulates cuBLAS/tensor-core operand conversion).
__device__ __forceinline__ float tf32r(float x) {
    uint32_t u;
    asm("cvt.rna.tf32.f32 %0, %1;" : "=r"(u) : "f"(x));
    return __uint_as_float(u);
}

// order-preserving float->uint key
__device__ __forceinline__ unsigned fkey(float d) {
    unsigned u = __float_as_uint(d);
    return (u & 0x80000000u) ? ~u : (u | 0x80000000u);
}

__device__ __forceinline__ void mma_tf32(float& c0, float& c1, float& c2, float& c3,
                                         uint32_t a0, uint32_t a1, uint32_t a2, uint32_t a3,
                                         uint32_t b0, uint32_t b1) {
    asm volatile("mma.sync.aligned.m16n8k8.row.col.f32.tf32.tf32.f32 "
                 "{%0,%1,%2,%3}, {%4,%5,%6,%7}, {%8,%9}, {%0,%1,%2,%3};"
                 : "+f"(c0), "+f"(c1), "+f"(c2), "+f"(c3)
                 : "r"(a0), "r"(a1), "r"(a2), "r"(a3), "r"(b0), "r"(b1));
}

// ---------------- K1: KNN (one warp per query point), exact fp32 ----------
__global__ __launch_bounds__(256) void knn_kernel(const float* __restrict__ xyz) {
    int warp = (blockIdx.x * blockDim.x + threadIdx.x) >> 5;
    int lane = threadIdx.x & 31;
    int b = warp >> 13;
    int n = warp & (Nq - 1);
    const float* xb = xyz + (size_t)b * Nq * 3;
    float qx = xb[n*3+0], qy = xb[n*3+1], qz = xb[n*3+2];
    float sqn = __fmaf_rn(qz, qz, __fmaf_rn(qy, qy, __fmul_rn(qx, qx)));

    float kd[Kq];
    int   ki[Kq];
#pragma unroll
    for (int i = 0; i < Kq; i++) { kd[i] = 1e30f; ki[i] = 0x7fffffff; }

    for (int m = lane; m < Nq; m += 32) {
        if (m == n) continue;
        float px = xb[m*3+0], py = xb[m*3+1], pz = xb[m*3+2];
        float sqm = __fmaf_rn(pz, pz, __fmaf_rn(py, py, __fmul_rn(px, px)));
        float dot = __fmaf_rn(qz, pz, __fmaf_rn(qy, py, __fmul_rn(qx, px)));
        float d = __fsub_rn(__fadd_rn(sqn, sqm), __fmul_rn(2.0f, dot));
        if (d < kd[Kq-1] || (d == kd[Kq-1] && m < ki[Kq-1])) {
            int j = Kq - 1;
            while (j > 0 && (kd[j-1] > d || (kd[j-1] == d && ki[j-1] > m))) {
                kd[j] = kd[j-1]; ki[j] = ki[j-1]; j--;
            }
            kd[j] = d; ki[j] = m;
        }
    }

    int p = 0;
    for (int t = 0; t < Kq; t++) {
        float myd; int myi;
        if (p < Kq) { myd = kd[p]; myi = ki[p]; } else { myd = 1e38f; myi = 0x7fffffff; }
        unsigned long long key = (((unsigned long long)fkey(myd)) << 32) | (unsigned)myi;
        unsigned long long mk = key;
#pragma unroll
        for (int off = 16; off; off >>= 1) {
            unsigned long long o = __shfl_xor_sync(0xffffffffu, mk, off);
            if (o < mk) mk = o;
        }
        if (mk == key) p++;
        if (lane == 0) g_idx[warp * Kq + t] = (int)(unsigned)(mk & 0xffffffffu);
    }
}

// ---------------- K2: build Fmat ----------------
__global__ __launch_bounds__(256) void fmat_kernel(const float* __restrict__ xyz,
                                                   const float* __restrict__ f) {
    int j = blockIdx.x * blockDim.x + threadIdx.x;
    int n = (j >> 4) & (Nq - 1);
    int b = j >> 17;
    int m = g_idx[j];
    const float* xb = xyz + (size_t)b * Nq * 3;
    float cx = xb[n*3+0], cy = xb[n*3+1], cz = xb[n*3+2];
    float px = xb[m*3+0], py = xb[m*3+1], pz = xb[m*3+2];
    float dx = px - cx, dy = py - cy, dz = pz - cz;
    float dist = sqrtf(dx*dx + dy*dy + dz*dz);

    const float* fb = f + (size_t)b * Cq * Nq;
#pragma unroll 4
    for (int c = 0; c < Cq; c++) {
        float gf  = fb[c*Nq + m];
        float cfv = fb[c*Nq + n];
        g_fmat[(size_t)c*CKq + j]        = gf;
        g_fmat[(size_t)(Cq + c)*CKq + j] = cfv;
        g_fmat[(size_t)(2*Cq + c)*CKq + j] = cfv - gf;
    }
    g_fmat[(size_t)96*CKq + j] = dx;
    g_fmat[(size_t)97*CKq + j] = dy;
    g_fmat[(size_t)98*CKq + j] = dz;
    g_fmat[(size_t)99*CKq + j] = px;
    g_fmat[(size_t)100*CKq + j] = py;
    g_fmat[(size_t)101*CKq + j] = pz;
    g_fmat[(size_t)102*CKq + j] = cx;
    g_fmat[(size_t)103*CKq + j] = cy;
    g_fmat[(size_t)104*CKq + j] = cz;
    g_fmat[(size_t)105*CKq + j] = dist;
}

// ---------------- K3: gather R columns from Fmat via r_indice ----------------
__global__ __launch_bounds__(256) void rgather_kernel(const int* __restrict__ rind) {
    int e = blockIdx.x * blockDim.x + threadIdx.x;
    if (e >= CFq * NRq) return;
    int cf  = e >> 16;
    int col = e & (NRq - 1);
    int nb  = col >> 2;
    int r   = col & 3;
    int b   = nb >> 13;
    int n   = nb & (Nq - 1);
    int ri  = rind[(((size_t)b*CFq + cf)*Nq + n)*Rq + r];
    g_rmat[(size_t)cf*NRq + col] = g_fmat[(size_t)cf*CKq + (size_t)nb*Kq + ri];
}

// ---------------- K4: tensor-core TF32 GEMM + bias + ReLU (+ fused l-max) ----
// Block tile 128x128, BK=16 (7 chunks over KPAD=112), 8 warps of 32x64.
// MODE 0: [Wh;Wl] @ Fmat -> h rows to g_hl, l rows max-reduced to g_lmax.
// MODE 1: Wg @ Rmat -> g_gm.
template <int MODE>
__global__ __launch_bounds__(256) void gemm_mma_kernel(
    const float* __restrict__ W0, const float* __restrict__ b0,
    const float* __restrict__ W1, const float* __restrict__ b1)
{
    const int NC = (MODE == 0) ? CKq : NRq;
    const float* __restrict__ Bm = (MODE == 0) ? g_fmat : g_rmat;

    // fragment-major smem: one LDS.128 per A-frag, one LDS.64 per B-frag
    __shared__ float As[8][2][128];   // [m16-tile][k8-step][lane*4 + pos]
    __shared__ float Bs[16][2][64];   // [n8-tile][k8-step][lane*2 + pos]

    int row0 = blockIdx.x * 128;
    int col0 = blockIdx.y * 128;
    bool lmode = (MODE == 0) && (row0 >= Hq);

    const float* W;
    const float* bias;
    if (lmode)  { W = W1 + (size_t)(row0 - Hq)*CFq; bias = b1 + (row0 - Hq); }
    else        { W = W0 + (size_t)row0*CFq;        bias = b0 + row0; }

    int tid  = threadIdx.x;
    int wid  = tid >> 5;
    int lane = tid & 31;
    int warp_m = wid >> 1;          // 0..3
    int warp_n = wid & 1;           // 0..1
    int gid = lane >> 2;            // 0..7
    int tig = lane & 3;             // 0..3

    float acc[2][8][4];
#pragma unroll
    for (int mi = 0; mi < 2; mi++)
#pragma unroll
        for (int ni = 0; ni < 8; ni++)
#pragma unroll
            for (int q = 0; q < 4; q++) acc[mi][ni][q] = 0.0f;

    for (int ch = 0; ch < 7; ch++) {
        int kbase = ch * 16;
        if (ch) __syncthreads();

        // fill A: thread t -> row m = t>>1, kk = (t&1)*8 .. +8
        {
            int m = tid >> 1;
            int kk0 = (tid & 1) * 8;
            int mtile = m >> 4, mr = m & 15;
            int agid = mr & 7, amhi = mr >> 3;
#pragma unroll
            for (int kk2 = 0; kk2 < 8; kk2++) {
                int kk = kk0 + kk2;
                int cf = kbase + kk;
                float v = (cf < CFq) ? tf32r(W[(size_t)m*CFq + cf]) : 0.0f;
                int kstep = kk >> 3, kr = kk & 7;
                int atig = kr & 3, akhi = kr >> 2;
                As[mtile][kstep][(agid*4 + atig)*4 + (amhi + 2*akhi)] = v;
            }
        }
        // fill B: thread t -> col n = t&127, kk = (t>>7)*8 .. +8
        {
            int n = tid & 127;
            int kk0 = (tid >> 7) * 8;
            int ntile = n >> 3, bgid = n & 7;
#pragma unroll
            for (int kk2 = 0; kk2 < 8; kk2++) {
                int kk = kk0 + kk2;
                int cf = kbase + kk;
                float v = (cf < CFq) ? tf32r(Bm[(size_t)cf*NC + col0 + n]) : 0.0f;
                int kstep = kk >> 3, kr = kk & 7;
                int btig = kr & 3, bkhi = kr >> 2;
                Bs[ntile][kstep][(bgid*4 + btig)*2 + bkhi] = v;
            }
        }
        __syncthreads();

#pragma unroll
        for (int ks = 0; ks < 2; ks++) {
            uint32_t a[2][4];
#pragma unroll
            for (int mi = 0; mi < 2; mi++) {
                float4 av = *(const float4*)&As[warp_m*2 + mi][ks][lane*4];
                a[mi][0] = __float_as_uint(av.x); a[mi][1] = __float_as_uint(av.y);
                a[mi][2] = __float_as_uint(av.z); a[mi][3] = __float_as_uint(av.w);
            }
#pragma unroll
            for (int ni = 0; ni < 8; ni++) {
                float2 bv = *(const float2*)&Bs[warp_n*8 + ni][ks][lane*2];
                uint32_t bb0 = __float_as_uint(bv.x), bb1 = __float_as_uint(bv.y);
#pragma unroll
                for (int mi = 0; mi < 2; mi++)
                    mma_tf32(acc[mi][ni][0], acc[mi][ni][1], acc[mi][ni][2], acc[mi][ni][3],
                             a[mi][0], a[mi][1], a[mi][2], a[mi][3], bb0, bb1);
            }
        }
    }

    // epilogue: bias + relu
#pragma unroll
    for (int mi = 0; mi < 2; mi++) {
        int rl0 = warp_m*32 + mi*16 + gid;     // local row for c0,c1
        float bb_lo = bias[rl0];
        float bb_hi = bias[rl0 + 8];
#pragma unroll
        for (int ni = 0; ni < 8; ni++) {
            acc[mi][ni][0] = fmaxf(acc[mi][ni][0] + bb_lo, 0.0f);
            acc[mi][ni][1] = fmaxf(acc[mi][ni][1] + bb_lo, 0.0f);
            acc[mi][ni][2] = fmaxf(acc[mi][ni][2] + bb_hi, 0.0f);
            acc[mi][ni][3] = fmaxf(acc[mi][ni][3] + bb_hi, 0.0f);
        }
    }

    if (!lmode) {
        float* __restrict__ Out = (MODE == 0) ? g_hl : g_gm;
#pragma unroll
        for (int mi = 0; mi < 2; mi++) {
            int row = row0 + warp_m*32 + mi*16 + gid;
#pragma unroll
            for (int ni = 0; ni < 8; ni++) {
                int col = col0 + warp_n*64 + ni*8 + tig*2;
                float2 vlo = make_float2(acc[mi][ni][0], acc[mi][ni][1]);
                float2 vhi = make_float2(acc[mi][ni][2], acc[mi][ni][3]);
                *(float2*)&Out[(size_t)row*NC + col]       = vlo;
                *(float2*)&Out[(size_t)(row+8)*NC + col]   = vhi;
            }
        }
    } else {
        // l rows: max over the 16 k-columns of each point (4 points per warp)
#pragma unroll
        for (int mi = 0; mi < 2; mi++) {
#pragma unroll
            for (int p = 0; p < 4; p++) {
                float vlo = fmaxf(fmaxf(acc[mi][2*p][0], acc[mi][2*p][1]),
                                  fmaxf(acc[mi][2*p+1][0], acc[mi][2*p+1][1]));
                float vhi = fmaxf(fmaxf(acc[mi][2*p][2], acc[mi][2*p][3]),
                                  fmaxf(acc[mi][2*p+1][2], acc[mi][2*p+1][3]));
                // reduce across tig (lane bits 0,1)
#pragma unroll
                for (int off = 1; off <= 2; off <<= 1) {
                    vlo = fmaxf(vlo, __shfl_xor_sync(0xffffffffu, vlo, off));
                    vhi = fmaxf(vhi, __shfl_xor_sync(0xffffffffu, vhi, off));
                }
                if (tig == 0) {
                    int pt = (col0 >> 4) + warp_n*4 + p;
                    int lrow = (row0 - Hq) + warp_m*32 + mi*16 + gid;
                    g_lmax[(size_t)pt*Hq + lrow]     = vlo;
                    g_lmax[(size_t)pt*Hq + lrow + 8] = vhi;
                }
            }
        }
    }
}

// ---------------- K5: finalize (lmax bcast, scores, softmax, aff) ----------
__global__ __launch_bounds__(128) void finalize_kernel(float* __restrict__ out) {
    __shared__ float gs[Hq][4];      // tf32-rounded g
    __shared__ float hs[Hq][16];     // tf32-rounded h
    __shared__ float gx[3][16];      // tf32-rounded grouped_xyz
    __shared__ float sc_part[128];

    int nb = blockIdx.x;
    int b = nb >> 13;
    int n = nb & (Nq - 1);
    int tid = threadIdx.x;
    size_t cb = (size_t)nb * Kq;

    for (int h = tid; h < Hq; h += 128) {
        float4 gv = *(const float4*)&g_gm[(size_t)h*NRq + (size_t)nb*Rq];
        gs[h][0] = tf32r(gv.x); gs[h][1] = tf32r(gv.y);
        gs[h][2] = tf32r(gv.z); gs[h][3] = tf32r(gv.w);
#pragma unroll
        for (int q = 0; q < 4; q++) {
            float4 hv = *(const float4*)&g_hl[(size_t)h*CKq + cb + q*4];
            hs[h][q*4+0] = tf32r(hv.x); hs[h][q*4+1] = tf32r(hv.y);
            hs[h][q*4+2] = tf32r(hv.z); hs[h][q*4+3] = tf32r(hv.w);
        }
        float lmx = g_lmax[(size_t)nb*Hq + h];
        float4 o; o.x = lmx; o.y = lmx; o.z = lmx; o.w = lmx;
        *(float4*)&out[OF_BASE + (((size_t)b*515 + h)*Nq + n)*Rq] = o;
    }
    if (tid < 48) {
        int c = tid >> 4, k = tid & 15;
        gx[c][k] = tf32r(g_fmat[(size_t)(99 + c)*CKq + cb + k]);
    }
    __syncthreads();

    {
        int rk = tid & 63;
        int half = tid >> 6;
        int r = rk >> 4, k = rk & 15;
        float s = 0.0f;
        int h0 = half * 256;
#pragma unroll 8
        for (int h = h0; h < h0 + 256; h++) s = fmaf(gs[h][r], hs[h][k], s);
        sc_part[tid] = s;
    }
    __syncthreads();

    if (tid < 64) {
        int r = tid >> 4, k = tid & 15;
        float sv = sc_part[tid] + sc_part[tid + 64];
        float mx = sv;
#pragma unroll
        for (int off = 8; off; off >>= 1) mx = fmaxf(mx, __shfl_xor_sync(0xffffffffu, mx, off));
        float e = expf(sv - mx);
        float sum = e;
#pragma unroll
        for (int off = 8; off; off >>= 1) sum += __shfl_xor_sync(0xffffffffu, sum, off);
        float sim = tf32r(e / sum);
        float a0 = sim * gx[0][k];
        float a1 = sim * gx[1][k];
        float a2 = sim * gx[2][k];
#pragma unroll
        for (int off = 8; off; off >>= 1) {
            a0 += __shfl_xor_sync(0xffffffffu, a0, off);
            a1 += __shfl_xor_sync(0xffffffffu, a1, off);
            a2 += __shfl_xor_sync(0xffffffffu, a2, off);
        }
        if (k == 0) {
            size_t cbase = ((size_t)b*(Nq*Rq) + (size_t)n*Rq + r) * 3;
            out[cbase + 0] = a0;
            out[cbase + 1] = a1;
            out[cbase + 2] = a2;
            out[OF_BASE + (((size_t)b*515 + 512)*Nq + n)*Rq + r] = a0;
            out[OF_BASE + (((size_t)b*515 + 513)*Nq + n)*Rq + r] = a1;
            out[OF_BASE + (((size_t)b*515 + 514)*Nq + n)*Rq + r] = a2;
        }
    }
}

// ---------------- launch ----------------
extern "C" void kernel_launch(void* const* d_in, const int* in_sizes, int n_in,
                              void* d_out, int out_size) {
    const float* xyz  = (const float*)d_in[0];
    const float* f    = (const float*)d_in[1];
    const float* Wg   = (const float*)d_in[2];
    const float* bg   = (const float*)d_in[3];
    const float* Wh   = (const float*)d_in[4];
    const float* bh   = (const float*)d_in[5];
    const float* Wl   = (const float*)d_in[6];
    const float* bl   = (const float*)d_in[7];
    const int*   rind = (const int*)d_in[8];
    float* out = (float*)d_out;

    knn_kernel<<<(Bq*Nq)/8, 256>>>(xyz);
    fmat_kernel<<<CKq/256, 256>>>(xyz, f);
    rgather_kernel<<<(CFq*NRq + 255)/256, 256>>>(rind);
    gemm_mma_kernel<0><<<dim3((2*Hq)/128, CKq/128), 256>>>(Wh, bh, Wl, bl);
    gemm_mma_kernel<1><<<dim3(Hq/128, NRq/128), 256>>>(Wg, bg, Wg, bg);
    finalize_kernel<<<Bq*Nq, 128>>>(out);
}

// round 8
// speedup vs baseline: 2.2094x; 1.6350x over previous
#include <cuda_runtime.h>
#include <cstdint>
#include <cstddef>

// Problem constants
#define Bq 2
#define Nq 8192
#define Cq 32
#define Kq 16
#define Rq 4
#define Hq 512
#define CFq 106
#define CKq (Bq*Nq*Kq)         // 262144 total (n,k) columns
#define NRq (Bq*Nq*Rq)         // 65536 total (n,r) columns
#define NBq (Bq*Nq)            // 16384 points
#define OF_BASE (Bq*Nq*Rq*3)   // 196608 floats of coarse_xyz before output_feature

// ---------------- scratch (device globals; no allocation) ----------------
__device__ int   g_idx[Bq*Nq*Kq];                  // knn indices, sorted by (d, idx)
__device__ float g_fmat[(size_t)CFq*CKq];          // Fmat [cf][col], col=(b*N+n)*16+k
__device__ float g_h[(size_t)NBq*Hq*16];           // h point-major [pt][h][k]
__device__ float g_g[(size_t)NBq*Hq*4];            // g point-major [pt][h][r]
__device__ float g_lmax[(size_t)NBq*Hq];           // max_k relu(l) : [pt][h]

// TF32 rounding (emulates cuBLAS/tensor-core operand conversion).
__device__ __forceinline__ float tf32r(float x) {
    uint32_t u;
    asm("cvt.rna.tf32.f32 %0, %1;" : "=r"(u) : "f"(x));
    return __uint_as_float(u);
}

// order-preserving float->uint key
__device__ __forceinline__ unsigned fkey(float d) {
    unsigned u = __float_as_uint(d);
    return (u & 0x80000000u) ? ~u : (u | 0x80000000u);
}

__device__ __forceinline__ void mma_tf32(float& c0, float& c1, float& c2, float& c3,
                                         uint32_t a0, uint32_t a1, uint32_t a2, uint32_t a3,
                                         uint32_t b0, uint32_t b1) {
    asm volatile("mma.sync.aligned.m16n8k8.row.col.f32.tf32.tf32.f32 "
                 "{%0,%1,%2,%3}, {%4,%5,%6,%7}, {%8,%9}, {%0,%1,%2,%3};"
                 : "+f"(c0), "+f"(c1), "+f"(c2), "+f"(c3)
                 : "r"(a0), "r"(a1), "r"(a2), "r"(a3), "r"(b0), "r"(b1));
}

// ---------------- K1: KNN — branchless register top-16, u64 keys ----------
__global__ __launch_bounds__(256) void knn_kernel(const float* __restrict__ xyz) {
    int warp = (blockIdx.x * blockDim.x + threadIdx.x) >> 5;
    int lane = threadIdx.x & 31;
    int b = warp >> 13;
    int n = warp & (Nq - 1);
    const float* xb = xyz + (size_t)b * Nq * 3;
    float qx = xb[n*3+0], qy = xb[n*3+1], qz = xb[n*3+2];
    float sqn = __fmaf_rn(qz, qz, __fmaf_rn(qy, qy, __fmul_rn(qx, qx)));

    unsigned long long key[Kq];
#pragma unroll
    for (int i = 0; i < Kq; i++) key[i] = ~0ull;

    for (int m = lane; m < Nq; m += 32) {
        float px = xb[m*3+0], py = xb[m*3+1], pz = xb[m*3+2];
        float sqm = __fmaf_rn(pz, pz, __fmaf_rn(py, py, __fmul_rn(px, px)));
        float dot = __fmaf_rn(qz, pz, __fmaf_rn(qy, py, __fmul_rn(qx, px)));
        float d = __fsub_rn(__fadd_rn(sqn, sqm), __fmul_rn(2.0f, dot));
        unsigned long long c = (((unsigned long long)fkey(d)) << 32) | (unsigned)m;
        if (m == n) c = ~0ull;              // exclude self (sentinel never inserts)
        if (c < key[Kq-1]) {
            // branchless sorted insert, all-static indices (stays in registers)
#pragma unroll
            for (int j = Kq-1; j > 0; j--)
                key[j] = (c < key[j-1]) ? key[j-1] : ((c < key[j]) ? c : key[j]);
            key[0] = (c < key[0]) ? c : key[0];
        }
    }

    // merge: 16 rounds of warp-min + static register shift in owning lane
#pragma unroll 1
    for (int t = 0; t < Kq; t++) {
        unsigned long long mk = key[0];
#pragma unroll
        for (int off = 16; off; off >>= 1) {
            unsigned long long o = __shfl_xor_sync(0xffffffffu, mk, off);
            if (o < mk) mk = o;
        }
        if (key[0] == mk) {                 // unique keys -> exactly one lane
#pragma unroll
            for (int j = 0; j < Kq-1; j++) key[j] = key[j+1];
            key[Kq-1] = ~0ull;
        }
        if (lane == 0) g_idx[warp * Kq + t] = (int)(unsigned)(mk & 0xffffffffu);
    }
}

// ---------------- K2: build Fmat (thread per (b,n,k) column) ----------------
__global__ __launch_bounds__(256) void fmat_kernel(const float* __restrict__ xyz,
                                                   const float* __restrict__ f) {
    int j = blockIdx.x * blockDim.x + threadIdx.x;
    int n = (j >> 4) & (Nq - 1);
    int b = j >> 17;
    int m = g_idx[j];
    const float* xb = xyz + (size_t)b * Nq * 3;
    float cx = xb[n*3+0], cy = xb[n*3+1], cz = xb[n*3+2];
    float px = xb[m*3+0], py = xb[m*3+1], pz = xb[m*3+2];
    float dx = px - cx, dy = py - cy, dz = pz - cz;
    float dist = sqrtf(dx*dx + dy*dy + dz*dz);

    const float* fb = f + (size_t)b * Cq * Nq;
#pragma unroll 4
    for (int c = 0; c < Cq; c++) {
        float gf  = fb[c*Nq + m];
        float cfv = fb[c*Nq + n];
        g_fmat[(size_t)c*CKq + j]          = gf;
        g_fmat[(size_t)(Cq + c)*CKq + j]   = cfv;
        g_fmat[(size_t)(2*Cq + c)*CKq + j] = cfv - gf;
    }
    g_fmat[(size_t)96*CKq + j]  = dx;
    g_fmat[(size_t)97*CKq + j]  = dy;
    g_fmat[(size_t)98*CKq + j]  = dz;
    g_fmat[(size_t)99*CKq + j]  = px;
    g_fmat[(size_t)100*CKq + j] = py;
    g_fmat[(size_t)101*CKq + j] = pz;
    g_fmat[(size_t)102*CKq + j] = cx;
    g_fmat[(size_t)103*CKq + j] = cy;
    g_fmat[(size_t)104*CKq + j] = cz;
    g_fmat[(size_t)105*CKq + j] = dist;
}

// ---------------- K3: double-buffered TF32 mma GEMM + fused epilogues ------
// Block tile 128x128, BK=16 (7 chunks), 8 warps of 32x64.
// MODE 0: [Wh;Wl] @ Fmat -> h (point-major g_h), l rows -> g_lmax.
// MODE 1: Wg @ gather(Fmat, r_indice) -> g (point-major g_g).
template <int MODE>
__global__ __launch_bounds__(256, 2) void gemm_mma_kernel(
    const float* __restrict__ W0, const float* __restrict__ b0,
    const float* __restrict__ W1, const float* __restrict__ b1,
    const int* __restrict__ rind)
{
    __shared__ float As[2][8][2][128];   // [buf][m16-tile][k8-step][frag pos]
    __shared__ float Bs[2][16][2][64];   // [buf][n8-tile][k8-step][frag pos]

    int row0 = blockIdx.x * 128;
    int col0 = blockIdx.y * 128;
    bool lmode = (MODE == 0) && (row0 >= Hq);

    const float* W;
    const float* bias;
    if (lmode)  { W = W1 + (size_t)(row0 - Hq)*CFq; bias = b1 + (row0 - Hq); }
    else        { W = W0 + (size_t)row0*CFq;        bias = b0 + row0; }

    int tid  = threadIdx.x;
    int wid  = tid >> 5;
    int lane = tid & 31;
    int warp_m = wid >> 1;
    int warp_n = wid & 1;
    int gid = lane >> 2;
    int tig = lane & 3;

    // fill mappings (fragment-major)
    int m_f = tid >> 1;  int kk0A = (tid & 1) * 8;
    int mtileA = m_f >> 4;
    int mrA = m_f & 15;
    int baseA = (mrA & 7)*16 + (mrA >> 3);
    int kstepA = tid & 1;

    int n_f = tid & 127; int kk0B = (tid >> 7) * 8;
    int ntileB = n_f >> 3;
    int baseB = (n_f & 7)*8;
    int kstepB = tid >> 7;

    int colB = col0 + n_f;
    // MODE 1 gather precompute
    int fmbase = 0; size_t rbase = 0;
    if (MODE == 1) {
        int nb = colB >> 2;
        int rr = colB & 3;
        int bb = nb >> 13;
        int nn = nb & (Nq - 1);
        rbase  = ((size_t)bb*CFq*Nq + nn)*4 + rr;
        fmbase = nb*16;
    }

    float pA[8], pB[8];

#define LOAD_CHUNK(CH) do { int kb = (CH)*16;                                            \
    _Pragma("unroll") for (int t = 0; t < 8; t++) {                                      \
        int cf = kb + kk0A + t;                                                          \
        pA[t] = (cf < CFq) ? W[(size_t)m_f*CFq + cf] : 0.0f; }                           \
    _Pragma("unroll") for (int t = 0; t < 8; t++) {                                      \
        int cf = kb + kk0B + t;                                                          \
        if (MODE == 0) pB[t] = (cf < CFq) ? g_fmat[(size_t)cf*CKq + colB] : 0.0f;        \
        else { if (cf < CFq) { int ri = rind[rbase + (size_t)cf*(Nq*4)];                 \
                               pB[t] = g_fmat[(size_t)cf*CKq + fmbase + ri]; }           \
               else pB[t] = 0.0f; } }                                                    \
  } while (0)

#define STORE_CHUNK(BUF) do {                                                            \
    _Pragma("unroll") for (int t = 0; t < 8; t++)                                        \
        As[BUF][mtileA][kstepA][baseA + (t&3)*4 + (t>>2)*2] = tf32r(pA[t]);              \
    _Pragma("unroll") for (int t = 0; t < 8; t++)                                        \
        Bs[BUF][ntileB][kstepB][baseB + (t&3)*2 + (t>>2)] = tf32r(pB[t]);                \
  } while (0)

    float acc[2][8][4];
#pragma unroll
    for (int mi = 0; mi < 2; mi++)
#pragma unroll
        for (int ni = 0; ni < 8; ni++)
#pragma unroll
            for (int q = 0; q < 4; q++) acc[mi][ni][q] = 0.0f;

    LOAD_CHUNK(0);
    STORE_CHUNK(0);
    __syncthreads();

#pragma unroll 1
    for (int ch = 0; ch < 7; ch++) {
        int cur = ch & 1;
        if (ch < 6) LOAD_CHUNK(ch + 1);
#pragma unroll
        for (int ks = 0; ks < 2; ks++) {
            uint32_t a[2][4];
#pragma unroll
            for (int mi = 0; mi < 2; mi++) {
                float4 av = *(const float4*)&As[cur][warp_m*2 + mi][ks][lane*4];
                a[mi][0] = __float_as_uint(av.x); a[mi][1] = __float_as_uint(av.y);
                a[mi][2] = __float_as_uint(av.z); a[mi][3] = __float_as_uint(av.w);
            }
#pragma unroll
            for (int ni = 0; ni < 8; ni++) {
                float2 bv = *(const float2*)&Bs[cur][warp_n*8 + ni][ks][lane*2];
                uint32_t bb0 = __float_as_uint(bv.x), bb1 = __float_as_uint(bv.y);
#pragma unroll
                for (int mi = 0; mi < 2; mi++)
                    mma_tf32(acc[mi][ni][0], acc[mi][ni][1], acc[mi][ni][2], acc[mi][ni][3],
                             a[mi][0], a[mi][1], a[mi][2], a[mi][3], bb0, bb1);
            }
        }
        if (ch < 6) STORE_CHUNK(cur ^ 1);
        __syncthreads();
    }
#undef LOAD_CHUNK
#undef STORE_CHUNK

    // bias + relu
#pragma unroll
    for (int mi = 0; mi < 2; mi++) {
        int rl0 = warp_m*32 + mi*16 + gid;
        float bb_lo = bias[rl0];
        float bb_hi = bias[rl0 + 8];
#pragma unroll
        for (int ni = 0; ni < 8; ni++) {
            acc[mi][ni][0] = fmaxf(acc[mi][ni][0] + bb_lo, 0.0f);
            acc[mi][ni][1] = fmaxf(acc[mi][ni][1] + bb_lo, 0.0f);
            acc[mi][ni][2] = fmaxf(acc[mi][ni][2] + bb_hi, 0.0f);
            acc[mi][ni][3] = fmaxf(acc[mi][ni][3] + bb_hi, 0.0f);
        }
    }

    if (MODE == 1) {
        // g point-major: g_g[(pt*Hq + row)*4 + r]
#pragma unroll
        for (int mi = 0; mi < 2; mi++) {
            int row = row0 + warp_m*32 + mi*16 + gid;
#pragma unroll
            for (int ni = 0; ni < 8; ni++) {
                int col = col0 + warp_n*64 + ni*8 + tig*2;
                int pt = col >> 2, r = col & 3;
                *(float2*)&g_g[((size_t)pt*Hq + row)*4 + r]     = make_float2(acc[mi][ni][0], acc[mi][ni][1]);
                *(float2*)&g_g[((size_t)pt*Hq + row + 8)*4 + r] = make_float2(acc[mi][ni][2], acc[mi][ni][3]);
            }
        }
    } else if (!lmode) {
        // h point-major: g_h[(pt*Hq + row)*16 + k]
#pragma unroll
        for (int mi = 0; mi < 2; mi++) {
            int row = row0 + warp_m*32 + mi*16 + gid;
#pragma unroll
            for (int ni = 0; ni < 8; ni++) {
                int col = col0 + warp_n*64 + ni*8 + tig*2;
                int pt = col >> 4, k = col & 15;
                *(float2*)&g_h[((size_t)pt*Hq + row)*16 + k]     = make_float2(acc[mi][ni][0], acc[mi][ni][1]);
                *(float2*)&g_h[((size_t)pt*Hq + row + 8)*16 + k] = make_float2(acc[mi][ni][2], acc[mi][ni][3]);
            }
        }
    } else {
        // l rows: max over the 16 k-columns of each point (4 points per warp)
#pragma unroll
        for (int mi = 0; mi < 2; mi++) {
#pragma unroll
            for (int p = 0; p < 4; p++) {
                float vlo = fmaxf(fmaxf(acc[mi][2*p][0], acc[mi][2*p][1]),
                                  fmaxf(acc[mi][2*p+1][0], acc[mi][2*p+1][1]));
                float vhi = fmaxf(fmaxf(acc[mi][2*p][2], acc[mi][2*p][3]),
                                  fmaxf(acc[mi][2*p+1][2], acc[mi][2*p+1][3]));
#pragma unroll
                for (int off = 1; off <= 2; off <<= 1) {
                    vlo = fmaxf(vlo, __shfl_xor_sync(0xffffffffu, vlo, off));
                    vhi = fmaxf(vhi, __shfl_xor_sync(0xffffffffu, vhi, off));
                }
                if (tig == 0) {
                    int pt = (col0 >> 4) + warp_n*4 + p;
                    int lrow = (row0 - Hq) + warp_m*32 + mi*16 + gid;
                    g_lmax[(size_t)pt*Hq + lrow]     = vlo;
                    g_lmax[(size_t)pt*Hq + lrow + 8] = vhi;
                }
            }
        }
    }
}

// ---------------- K4: finalize (streaming point-major loads) ---------------
__global__ __launch_bounds__(128) void finalize_kernel(float* __restrict__ out) {
    __shared__ float hs[Hq][16];     // tf32-rounded h
    __shared__ float gs[Hq][4];      // tf32-rounded g
    __shared__ float gx[3][16];      // tf32-rounded grouped_xyz
    __shared__ float sc_part[128];

    int nb = blockIdx.x;
    int b = nb >> 13;
    int n = nb & (Nq - 1);
    int tid = threadIdx.x;
    size_t cb = (size_t)nb * Kq;

    // stream h: 2048 float4, fully coalesced
    {
        const float4* src = (const float4*)(g_h + (size_t)nb * (Hq*16));
        float4* dst = (float4*)&hs[0][0];
        for (int i = tid; i < Hq*16/4; i += 128) {
            float4 v = src[i];
            v.x = tf32r(v.x); v.y = tf32r(v.y); v.z = tf32r(v.z); v.w = tf32r(v.w);
            dst[i] = v;
        }
    }
    // stream g: 512 float4
    {
        const float4* src = (const float4*)(g_g + (size_t)nb * (Hq*4));
        float4* dst = (float4*)&gs[0][0];
        for (int i = tid; i < Hq; i += 128) {
            float4 v = src[i];
            v.x = tf32r(v.x); v.y = tf32r(v.y); v.z = tf32r(v.z); v.w = tf32r(v.w);
            dst[i] = v;
        }
    }
    // l_prime from lmax (contiguous read)
    for (int h = tid; h < Hq; h += 128) {
        float lmx = g_lmax[(size_t)nb*Hq + h];
        float4 o; o.x = lmx; o.y = lmx; o.z = lmx; o.w = lmx;
        *(float4*)&out[OF_BASE + (((size_t)b*515 + h)*Nq + n)*Rq] = o;
    }
    if (tid < 48) {
        int c = tid >> 4, k = tid & 15;
        gx[c][k] = tf32r(g_fmat[(size_t)(99 + c)*CKq + cb + k]);
    }
    __syncthreads();

    // scores[r][k] = sum_h g[h][r]*h[h][k]
    {
        int rk = tid & 63;
        int half = tid >> 6;
        int r = rk >> 4, k = rk & 15;
        float s = 0.0f;
        int h0 = half * 256;
#pragma unroll 8
        for (int h = h0; h < h0 + 256; h++) s = fmaf(gs[h][r], hs[h][k], s);
        sc_part[tid] = s;
    }
    __syncthreads();

    if (tid < 64) {
        int r = tid >> 4, k = tid & 15;
        float sv = sc_part[tid] + sc_part[tid + 64];
        float mx = sv;
#pragma unroll
        for (int off = 8; off; off >>= 1) mx = fmaxf(mx, __shfl_xor_sync(0xffffffffu, mx, off));
        float e = expf(sv - mx);
        float sum = e;
#pragma unroll
        for (int off = 8; off; off >>= 1) sum += __shfl_xor_sync(0xffffffffu, sum, off);
        float sim = tf32r(e / sum);
        float a0 = sim * gx[0][k];
        float a1 = sim * gx[1][k];
        float a2 = sim * gx[2][k];
#pragma unroll
        for (int off = 8; off; off >>= 1) {
            a0 += __shfl_xor_sync(0xffffffffu, a0, off);
            a1 += __shfl_xor_sync(0xffffffffu, a1, off);
            a2 += __shfl_xor_sync(0xffffffffu, a2, off);
        }
        if (k == 0) {
            size_t cbase = ((size_t)b*(Nq*Rq) + (size_t)n*Rq + r) * 3;
            out[cbase + 0] = a0;
            out[cbase + 1] = a1;
            out[cbase + 2] = a2;
            out[OF_BASE + (((size_t)b*515 + 512)*Nq + n)*Rq + r] = a0;
            out[OF_BASE + (((size_t)b*515 + 513)*Nq + n)*Rq + r] = a1;
            out[OF_BASE + (((size_t)b*515 + 514)*Nq + n)*Rq + r] = a2;
        }
    }
}

// ---------------- launch ----------------
extern "C" void kernel_launch(void* const* d_in, const int* in_sizes, int n_in,
                              void* d_out, int out_size) {
    const float* xyz  = (const float*)d_in[0];
    const float* f    = (const float*)d_in[1];
    const float* Wg   = (const float*)d_in[2];
    const float* bg   = (const float*)d_in[3];
    const float* Wh   = (const float*)d_in[4];
    const float* bh   = (const float*)d_in[5];
    const float* Wl   = (const float*)d_in[6];
    const float* bl   = (const float*)d_in[7];
    const int*   rind = (const int*)d_in[8];
    float* out = (float*)d_out;

    knn_kernel<<<(Bq*Nq)/8, 256>>>(xyz);
    fmat_kernel<<<CKq/256, 256>>>(xyz, f);
    gemm_mma_kernel<0><<<dim3((2*Hq)/128, CKq/128), 256>>>(Wh, bh, Wl, bl, nullptr);
    gemm_mma_kernel<1><<<dim3(Hq/128, NRq/128), 256>>>(Wg, bg, Wg, bg, rind);
    finalize_kernel<<<NBq, 128>>>(out);
}

// round 9
// speedup vs baseline: 2.4119x; 1.0916x over previous
#include <cuda_runtime.h>
#include <cstdint>
#include <cstddef>

// Problem constants
#define Bq 2
#define Nq 8192
#define Cq 32
#define Kq 16
#define Rq 4
#define Hq 512
#define CFq 106
#define KP 112                 // padded K for GEMMs (7 chunks of 16)
#define CKq (Bq*Nq*Kq)         // 262144 total (n,k) columns
#define NRq (Bq*Nq*Rq)         // 65536 total (n,r) columns
#define NBq (Bq*Nq)            // 16384 points
#define OF_BASE (Bq*Nq*Rq*3)   // 196608 floats of coarse_xyz before output_feature

// ---------------- scratch (device globals; no allocation) ----------------
__device__ int   g_idx[Bq*Nq*Kq];                  // knn indices, sorted by (d, idx)
__device__ float g_fmat[(size_t)KP*CKq];           // tf32-rounded Fmat, rows 106..111 zero
__device__ float g_whl[1024*KP];                   // tf32-rounded [Wh;Wl], padded
__device__ float g_wg[Hq*KP];                      // tf32-rounded Wg, padded
__device__ float g_g[(size_t)NBq*Hq*4];            // tf32-rounded g point-major [pt][h][r]
__device__ float g_lmax[(size_t)NBq*Hq];           // max_k relu(l) : [pt][h]
__device__ float g_spart[(size_t)16*NBq*64];       // score partials [slab][pt][r][k]

// TF32 rounding (emulates cuBLAS/tensor-core operand conversion).
__device__ __forceinline__ float tf32r(float x) {
    uint32_t u;
    asm("cvt.rna.tf32.f32 %0, %1;" : "=r"(u) : "f"(x));
    return __uint_as_float(u);
}

// order-preserving float->uint key
__device__ __forceinline__ unsigned fkey(float d) {
    unsigned u = __float_as_uint(d);
    return (u & 0x80000000u) ? ~u : (u | 0x80000000u);
}

__device__ __forceinline__ void mma_tf32(float& c0, float& c1, float& c2, float& c3,
                                         uint32_t a0, uint32_t a1, uint32_t a2, uint32_t a3,
                                         uint32_t b0, uint32_t b1) {
    asm volatile("mma.sync.aligned.m16n8k8.row.col.f32.tf32.tf32.f32 "
                 "{%0,%1,%2,%3}, {%4,%5,%6,%7}, {%8,%9}, {%0,%1,%2,%3};"
                 : "+f"(c0), "+f"(c1), "+f"(c2), "+f"(c3)
                 : "r"(a0), "r"(a1), "r"(a2), "r"(a3), "r"(b0), "r"(b1));
}

// ---------------- K0: prep weights (round + pad to KP) ----------------
__global__ __launch_bounds__(256) void prep_weights(const float* __restrict__ Wh,
                                                    const float* __restrict__ Wl,
                                                    const float* __restrict__ Wg) {
    int i = blockIdx.x * blockDim.x + threadIdx.x;   // 0 .. 1536*112-1
    if (i >= 1536*KP) return;
    int row = i / KP, cf = i - row*KP;
    float v = 0.0f;
    if (cf < CFq) {
        if (row < 512)       v = Wh[row*CFq + cf];
        else if (row < 1024) v = Wl[(row-512)*CFq + cf];
        else                 v = Wg[(row-1024)*CFq + cf];
    }
    if (row < 1024) g_whl[row*KP + cf] = tf32r(v);
    else            g_wg[(row-1024)*KP + cf] = tf32r(v);
}

// ---------------- K1: KNN — smem-tiled candidates, register top-16 --------
#define TS 2048
__global__ __launch_bounds__(256) void knn_kernel(const float* __restrict__ xyz) {
    __shared__ float sp[TS*3];
    int tid = threadIdx.x;
    int wid = tid >> 5, lane = tid & 31;
    int gp = blockIdx.x * 8 + wid;         // global point id
    int b = gp >> 13;
    int n = gp & (Nq - 1);
    const float* xb = xyz + (size_t)b * Nq * 3;
    float qx = xb[n*3+0], qy = xb[n*3+1], qz = xb[n*3+2];
    float sqn = __fmaf_rn(qz, qz, __fmaf_rn(qy, qy, __fmul_rn(qx, qx)));

    unsigned long long key[Kq];
#pragma unroll
    for (int i = 0; i < Kq; i++) key[i] = ~0ull;

    for (int tile = 0; tile < Nq/TS; tile++) {
        __syncthreads();
        for (int i = tid; i < TS*3; i += 256) sp[i] = xb[tile*(TS*3) + i];
        __syncthreads();
#pragma unroll 1
        for (int m = lane; m < TS; m += 32) {
            float px = sp[m*3+0], py = sp[m*3+1], pz = sp[m*3+2];
            int mg = tile*TS + m;
            float sqm = __fmaf_rn(pz, pz, __fmaf_rn(py, py, __fmul_rn(px, px)));
            float dot = __fmaf_rn(qz, pz, __fmaf_rn(qy, py, __fmul_rn(qx, px)));
            float d = __fsub_rn(__fadd_rn(sqn, sqm), __fmul_rn(2.0f, dot));
            unsigned long long c = (((unsigned long long)fkey(d)) << 32) | (unsigned)mg;
            if (mg == n) c = ~0ull;
            if (c < key[Kq-1]) {
#pragma unroll
                for (int j = Kq-1; j > 0; j--)
                    key[j] = (c < key[j-1]) ? key[j-1] : ((c < key[j]) ? c : key[j]);
                key[0] = (c < key[0]) ? c : key[0];
            }
        }
    }

#pragma unroll 1
    for (int t = 0; t < Kq; t++) {
        unsigned long long mk = key[0];
#pragma unroll
        for (int off = 16; off; off >>= 1) {
            unsigned long long o = __shfl_xor_sync(0xffffffffu, mk, off);
            if (o < mk) mk = o;
        }
        if (key[0] == mk) {
#pragma unroll
            for (int j = 0; j < Kq-1; j++) key[j] = key[j+1];
            key[Kq-1] = ~0ull;
        }
        if (lane == 0) g_idx[gp * Kq + t] = (int)(unsigned)(mk & 0xffffffffu);
    }
}

// ---------------- K2: build Fmat (tf32-rounded, padded rows zero) ----------
__global__ __launch_bounds__(256) void fmat_kernel(const float* __restrict__ xyz,
                                                   const float* __restrict__ f) {
    int j = blockIdx.x * blockDim.x + threadIdx.x;
    int n = (j >> 4) & (Nq - 1);
    int b = j >> 17;
    int m = g_idx[j];
    const float* xb = xyz + (size_t)b * Nq * 3;
    float cx = xb[n*3+0], cy = xb[n*3+1], cz = xb[n*3+2];
    float px = xb[m*3+0], py = xb[m*3+1], pz = xb[m*3+2];
    float dx = px - cx, dy = py - cy, dz = pz - cz;
    float dist = sqrtf(dx*dx + dy*dy + dz*dz);

    const float* fb = f + (size_t)b * Cq * Nq;
#pragma unroll 4
    for (int c = 0; c < Cq; c++) {
        float gf  = fb[c*Nq + m];
        float cfv = fb[c*Nq + n];
        g_fmat[(size_t)c*CKq + j]          = tf32r(gf);
        g_fmat[(size_t)(Cq + c)*CKq + j]   = tf32r(cfv);
        g_fmat[(size_t)(2*Cq + c)*CKq + j] = tf32r(cfv - gf);
    }
    g_fmat[(size_t)96*CKq + j]  = tf32r(dx);
    g_fmat[(size_t)97*CKq + j]  = tf32r(dy);
    g_fmat[(size_t)98*CKq + j]  = tf32r(dz);
    g_fmat[(size_t)99*CKq + j]  = tf32r(px);
    g_fmat[(size_t)100*CKq + j] = tf32r(py);
    g_fmat[(size_t)101*CKq + j] = tf32r(pz);
    g_fmat[(size_t)102*CKq + j] = tf32r(cx);
    g_fmat[(size_t)103*CKq + j] = tf32r(cy);
    g_fmat[(size_t)104*CKq + j] = tf32r(cz);
    g_fmat[(size_t)105*CKq + j] = tf32r(dist);
#pragma unroll
    for (int c = 106; c < KP; c++) g_fmat[(size_t)c*CKq + j] = 0.0f;
}

// ---------------- K3: double-buffered TF32 mma GEMM + fused epilogues ------
// MODE 0: [Wh;Wl] @ Fmat. h rows -> fused score partials (needs g_g!);
//         l rows -> g_lmax.  MODE 1: Wg @ gather(Fmat) -> g_g (rounded).
template <int MODE>
__global__ __launch_bounds__(256, 2) void gemm_mma_kernel(
    const float* __restrict__ b0, const float* __restrict__ b1,
    const int* __restrict__ rind)
{
    __shared__ float As[2][8][2][128];
    __shared__ float Bs[2][16][2][64];

    int row0 = blockIdx.x * 128;
    int col0 = blockIdx.y * 128;
    bool lmode = (MODE == 0) && (row0 >= Hq);

    const float* W = (MODE == 0) ? (g_whl + (size_t)row0*KP) : (g_wg + (size_t)row0*KP);
    const float* bias = lmode ? (b1 + (row0 - Hq)) : (b0 + row0);

    int tid  = threadIdx.x;
    int wid  = tid >> 5;
    int lane = tid & 31;
    int warp_m = wid >> 1;
    int warp_n = wid & 1;
    int gid = lane >> 2;
    int tig = lane & 3;

    int m_f = tid >> 1;  int kk0A = (tid & 1) * 8;
    int mtileA = m_f >> 4;
    int mrA = m_f & 15;
    int baseA = (mrA & 7)*16 + (mrA >> 3);
    int kstepA = tid & 1;

    int n_f = tid & 127; int kk0B = (tid >> 7) * 8;
    int ntileB = n_f >> 3;
    int baseB = (n_f & 7)*8;
    int kstepB = tid >> 7;

    int colB = col0 + n_f;
    int fmbase = 0; size_t rbase = 0;
    if (MODE == 1) {
        int nb = colB >> 2;
        int rr = colB & 3;
        int bb = nb >> 13;
        int nn = nb & (Nq - 1);
        rbase  = ((size_t)bb*CFq*Nq + nn)*4 + rr;
        fmbase = nb*16;
    }

    float pA[8], pB[8];

#define LOAD_CHUNK(CH) do { int kb = (CH)*16;                                            \
    float4 a0v = *(const float4*)&W[(size_t)m_f*KP + kb + kk0A];                         \
    float4 a1v = *(const float4*)&W[(size_t)m_f*KP + kb + kk0A + 4];                     \
    pA[0]=a0v.x; pA[1]=a0v.y; pA[2]=a0v.z; pA[3]=a0v.w;                                  \
    pA[4]=a1v.x; pA[5]=a1v.y; pA[6]=a1v.z; pA[7]=a1v.w;                                  \
    _Pragma("unroll") for (int t = 0; t < 8; t++) {                                      \
        int cf = kb + kk0B + t;                                                          \
        if (MODE == 0) pB[t] = g_fmat[(size_t)cf*CKq + colB];                            \
        else { if (cf < CFq) { int ri = rind[rbase + (size_t)cf*(Nq*4)];                 \
                               pB[t] = g_fmat[(size_t)cf*CKq + fmbase + ri]; }           \
               else pB[t] = 0.0f; } }                                                    \
  } while (0)

#define STORE_CHUNK(BUF) do {                                                            \
    _Pragma("unroll") for (int t = 0; t < 8; t++)                                        \
        As[BUF][mtileA][kstepA][baseA + (t&3)*4 + (t>>2)*2] = pA[t];                     \
    _Pragma("unroll") for (int t = 0; t < 8; t++)                                        \
        Bs[BUF][ntileB][kstepB][baseB + (t&3)*2 + (t>>2)] = pB[t];                       \
  } while (0)

    float acc[2][8][4];
#pragma unroll
    for (int mi = 0; mi < 2; mi++)
#pragma unroll
        for (int ni = 0; ni < 8; ni++)
#pragma unroll
            for (int q = 0; q < 4; q++) acc[mi][ni][q] = 0.0f;

    LOAD_CHUNK(0);
    STORE_CHUNK(0);
    __syncthreads();

#pragma unroll 1
    for (int ch = 0; ch < 7; ch++) {
        int cur = ch & 1;
        if (ch < 6) LOAD_CHUNK(ch + 1);
#pragma unroll
        for (int ks = 0; ks < 2; ks++) {
            uint32_t a[2][4];
#pragma unroll
            for (int mi = 0; mi < 2; mi++) {
                float4 av = *(const float4*)&As[cur][warp_m*2 + mi][ks][lane*4];
                a[mi][0] = __float_as_uint(av.x); a[mi][1] = __float_as_uint(av.y);
                a[mi][2] = __float_as_uint(av.z); a[mi][3] = __float_as_uint(av.w);
            }
#pragma unroll
            for (int ni = 0; ni < 8; ni++) {
                float2 bv = *(const float2*)&Bs[cur][warp_n*8 + ni][ks][lane*2];
                uint32_t bb0 = __float_as_uint(bv.x), bb1 = __float_as_uint(bv.y);
#pragma unroll
                for (int mi = 0; mi < 2; mi++)
                    mma_tf32(acc[mi][ni][0], acc[mi][ni][1], acc[mi][ni][2], acc[mi][ni][3],
                             a[mi][0], a[mi][1], a[mi][2], a[mi][3], bb0, bb1);
            }
        }
        if (ch < 6) STORE_CHUNK(cur ^ 1);
        __syncthreads();
    }
#undef LOAD_CHUNK
#undef STORE_CHUNK

    // bias + relu
#pragma unroll
    for (int mi = 0; mi < 2; mi++) {
        int rl0 = warp_m*32 + mi*16 + gid;
        float bb_lo = bias[rl0];
        float bb_hi = bias[rl0 + 8];
#pragma unroll
        for (int ni = 0; ni < 8; ni++) {
            acc[mi][ni][0] = fmaxf(acc[mi][ni][0] + bb_lo, 0.0f);
            acc[mi][ni][1] = fmaxf(acc[mi][ni][1] + bb_lo, 0.0f);
            acc[mi][ni][2] = fmaxf(acc[mi][ni][2] + bb_hi, 0.0f);
            acc[mi][ni][3] = fmaxf(acc[mi][ni][3] + bb_hi, 0.0f);
        }
    }

    if (MODE == 1) {
        // g point-major, stored tf32-rounded (only consumer is scores)
#pragma unroll
        for (int mi = 0; mi < 2; mi++) {
            int row = row0 + warp_m*32 + mi*16 + gid;
#pragma unroll
            for (int ni = 0; ni < 8; ni++) {
                int col = col0 + warp_n*64 + ni*8 + tig*2;
                int pt = col >> 2, r = col & 3;
                *(float2*)&g_g[((size_t)pt*Hq + row)*4 + r] =
                    make_float2(tf32r(acc[mi][ni][0]), tf32r(acc[mi][ni][1]));
                *(float2*)&g_g[((size_t)pt*Hq + row + 8)*4 + r] =
                    make_float2(tf32r(acc[mi][ni][2]), tf32r(acc[mi][ni][3]));
            }
        }
    } else if (!lmode) {
        // fused score partials: s[r][k] = sum_rows g[row][r] * tf32r(h[row][k])
        int slab = blockIdx.x*4 + warp_m;          // 16 row-slabs of 32 rows
        int rowbase = row0 + warp_m*32 + gid;
#pragma unroll 1
        for (int p = 0; p < 4; p++) {
            int pt = (col0 >> 4) + warp_n*4 + p;
            float4 grow[4];
#pragma unroll
            for (int q = 0; q < 4; q++)
                grow[q] = *(const float4*)&g_g[((size_t)pt*Hq + rowbase + q*8)*4];
            float s[4][4];
#pragma unroll
            for (int r = 0; r < 4; r++)
#pragma unroll
                for (int kk = 0; kk < 4; kk++) s[r][kk] = 0.0f;
#pragma unroll
            for (int q = 0; q < 4; q++) {
                int mi = q >> 1, hi = q & 1;
                float h0 = tf32r(acc[mi][2*p  ][hi*2+0]);
                float h1 = tf32r(acc[mi][2*p  ][hi*2+1]);
                float h2 = tf32r(acc[mi][2*p+1][hi*2+0]);
                float h3 = tf32r(acc[mi][2*p+1][hi*2+1]);
                float gr[4] = {grow[q].x, grow[q].y, grow[q].z, grow[q].w};
#pragma unroll
                for (int r = 0; r < 4; r++) {
                    s[r][0] = fmaf(gr[r], h0, s[r][0]);
                    s[r][1] = fmaf(gr[r], h1, s[r][1]);
                    s[r][2] = fmaf(gr[r], h2, s[r][2]);
                    s[r][3] = fmaf(gr[r], h3, s[r][3]);
                }
            }
            // reduce over gid (lane bits 2..4)
#pragma unroll
            for (int off = 4; off <= 16; off <<= 1)
#pragma unroll
                for (int r = 0; r < 4; r++)
#pragma unroll
                    for (int kk = 0; kk < 4; kk++)
                        s[r][kk] += __shfl_xor_sync(0xffffffffu, s[r][kk], off);
            if (gid == 0) {
                size_t base = ((size_t)slab*NBq + pt)*64;
#pragma unroll
                for (int r = 0; r < 4; r++) {
                    *(float2*)&g_spart[base + r*16 + 2*tig]     = make_float2(s[r][0], s[r][1]);
                    *(float2*)&g_spart[base + r*16 + 8 + 2*tig] = make_float2(s[r][2], s[r][3]);
                }
            }
        }
    } else {
        // l rows: max over the 16 k-columns of each point
#pragma unroll
        for (int mi = 0; mi < 2; mi++) {
#pragma unroll
            for (int p = 0; p < 4; p++) {
                float vlo = fmaxf(fmaxf(acc[mi][2*p][0], acc[mi][2*p][1]),
                                  fmaxf(acc[mi][2*p+1][0], acc[mi][2*p+1][1]));
                float vhi = fmaxf(fmaxf(acc[mi][2*p][2], acc[mi][2*p][3]),
                                  fmaxf(acc[mi][2*p+1][2], acc[mi][2*p+1][3]));
#pragma unroll
                for (int off = 1; off <= 2; off <<= 1) {
                    vlo = fmaxf(vlo, __shfl_xor_sync(0xffffffffu, vlo, off));
                    vhi = fmaxf(vhi, __shfl_xor_sync(0xffffffffu, vhi, off));
                }
                if (tig == 0) {
                    int pt = (col0 >> 4) + warp_n*4 + p;
                    int lrow = (row0 - Hq) + warp_m*32 + mi*16 + gid;
                    g_lmax[(size_t)pt*Hq + lrow]     = vlo;
                    g_lmax[(size_t)pt*Hq + lrow + 8] = vhi;
                }
            }
        }
    }
}

// ---------------- K4: finalize (sum partials, softmax, aff, outputs) -------
__global__ __launch_bounds__(128) void finalize_kernel(float* __restrict__ out) {
    __shared__ float gx[3][16];

    int nb = blockIdx.x;
    int b = nb >> 13;
    int n = nb & (Nq - 1);
    int tid = threadIdx.x;
    size_t cb = (size_t)nb * Kq;

    // l_prime
    for (int h = tid; h < Hq; h += 128) {
        float lmx = g_lmax[(size_t)nb*Hq + h];
        float4 o; o.x = lmx; o.y = lmx; o.z = lmx; o.w = lmx;
        *(float4*)&out[OF_BASE + (((size_t)b*515 + h)*Nq + n)*Rq] = o;
    }
    if (tid < 48) {
        int c = tid >> 4, k = tid & 15;
        gx[c][k] = g_fmat[(size_t)(99 + c)*CKq + cb + k];   // already tf32-rounded
    }
    __syncthreads();

    if (tid < 64) {
        int r = tid >> 4, k = tid & 15;
        float sv = 0.0f;
#pragma unroll
        for (int slab = 0; slab < 16; slab++)
            sv += g_spart[((size_t)slab*NBq + nb)*64 + tid];
        float mx = sv;
#pragma unroll
        for (int off = 8; off; off >>= 1) mx = fmaxf(mx, __shfl_xor_sync(0xffffffffu, mx, off));
        float e = expf(sv - mx);
        float sum = e;
#pragma unroll
        for (int off = 8; off; off >>= 1) sum += __shfl_xor_sync(0xffffffffu, sum, off);
        float sim = tf32r(e / sum);
        float a0 = sim * gx[0][k];
        float a1 = sim * gx[1][k];
        float a2 = sim * gx[2][k];
#pragma unroll
        for (int off = 8; off; off >>= 1) {
            a0 += __shfl_xor_sync(0xffffffffu, a0, off);
            a1 += __shfl_xor_sync(0xffffffffu, a1, off);
            a2 += __shfl_xor_sync(0xffffffffu, a2, off);
        }
        if (k == 0) {
            size_t cbase = ((size_t)b*(Nq*Rq) + (size_t)n*Rq + r) * 3;
            out[cbase + 0] = a0;
            out[cbase + 1] = a1;
            out[cbase + 2] = a2;
            out[OF_BASE + (((size_t)b*515 + 512)*Nq + n)*Rq + r] = a0;
            out[OF_BASE + (((size_t)b*515 + 513)*Nq + n)*Rq + r] = a1;
            out[OF_BASE + (((size_t)b*515 + 514)*Nq + n)*Rq + r] = a2;
        }
    }
}

// ---------------- launch ----------------
extern "C" void kernel_launch(void* const* d_in, const int* in_sizes, int n_in,
                              void* d_out, int out_size) {
    const float* xyz  = (const float*)d_in[0];
    const float* f    = (const float*)d_in[1];
    const float* Wg   = (const float*)d_in[2];
    const float* bg   = (const float*)d_in[3];
    const float* Wh   = (const float*)d_in[4];
    const float* bh   = (const float*)d_in[5];
    const float* Wl   = (const float*)d_in[6];
    const float* bl   = (const float*)d_in[7];
    const int*   rind = (const int*)d_in[8];
    float* out = (float*)d_out;

    prep_weights<<<(1536*KP + 255)/256, 256>>>(Wh, Wl, Wg);
    knn_kernel<<<NBq/8, 256>>>(xyz);
    fmat_kernel<<<CKq/256, 256>>>(xyz, f);
    gemm_mma_kernel<1><<<dim3(Hq/128, NRq/128), 256>>>(bg, bg, rind);      // g first
    gemm_mma_kernel<0><<<dim3((2*Hq)/128, CKq/128), 256>>>(bh, bl, nullptr); // h/l + scores
    finalize_kernel<<<NBq, 128>>>(out);
}